// round 4
// baseline (speedup 1.0000x reference)
#include <cuda_runtime.h>
#include <math.h>

// Problem dims
#define H   2048
#define V   50257
#define L   512
#define H3  6144
#define C2  4096   // 2*H

#define HH_BLOCKS  (H3 / 8)   // 768 blocks for W_hh gates (8 rows/block)
#define ATT_BLOCKS (L / 8)    // 64 blocks for attention logits

// ---------------- device scratch ----------------
__device__ float g_att[H];           // attn_applied (atomic-accumulated)
__device__ float g_attn_logits[L];
__device__ float g_attn_weights[L];
__device__ float g_x[H];             // relu(combined)
__device__ float g_gates[2 * H3];    // ih gates [0,6144), hh gates [6144,12288)
__device__ float g_h1[H];
__device__ float g_logits[V];
__device__ float g_sumexp;
__device__ unsigned g_cnt = 0;

__device__ __forceinline__ float warp_reduce(float v) {
#pragma unroll
    for (int o = 16; o > 0; o >>= 1)
        v += __shfl_xor_sync(0xFFFFFFFFu, v, o);
    return v;
}

__device__ __forceinline__ float dot4(float4 a, float4 v) {
    return a.x * v.x + a.y * v.y + a.z * v.z + a.w * v.w;
}

// ---------------- launch 1: fused W_hh gates + attention logits ----------------
// Both depend only on kernel inputs. blocks [0,768): W_hh matvec (6144x2048 on
// hidden). blocks [768,832): attn logits (512x4096 on [emb[input];hidden]).
__global__ void k_fused1(const float* __restrict__ W_hh,
                         const float* __restrict__ b_hh,
                         const float* __restrict__ hidden,
                         const float* __restrict__ attn_W,
                         const float* __restrict__ attn_b,
                         const float* __restrict__ emb,
                         const int* __restrict__ input) {
    __shared__ float4 sx[C2 / 4];    // 16KB; hh branch uses first 8KB
    int tid = threadIdx.x;
    int wib = tid >> 5, lane = tid & 31;
    int blk = blockIdx.x;

    if (blk < HH_BLOCKS) {
        const float4* h4 = (const float4*)hidden;
        for (int i = tid; i < H / 4; i += 256) sx[i] = h4[i];
        __syncthreads();
        int row = blk * 8 + wib;
        const float4* w4 = (const float4*)(W_hh + (size_t)row * H);
        float acc0 = 0.f, acc1 = 0.f;
#pragma unroll
        for (int k = 0; k < 16; k += 2) {
            float4 a  = w4[lane + (k + 0) * 32];
            float4 v  = sx[lane + (k + 0) * 32];
            acc0 += dot4(a, v);
            float4 a2 = w4[lane + (k + 1) * 32];
            float4 v2 = sx[lane + (k + 1) * 32];
            acc1 += dot4(a2, v2);
        }
        float acc = warp_reduce(acc0 + acc1);
        if (lane == 0) g_gates[H3 + row] = acc + b_hh[row];
    } else {
        const float4* e4 = (const float4*)(emb + (size_t)input[0] * H);
        const float4* h4 = (const float4*)hidden;
        for (int i = tid; i < C2 / 4; i += 256)
            sx[i] = (i < H / 4) ? e4[i] : h4[i - H / 4];
        __syncthreads();
        int row = (blk - HH_BLOCKS) * 8 + wib;
        const float4* w4 = (const float4*)(attn_W + (size_t)row * C2);
        float acc0 = 0.f, acc1 = 0.f;
#pragma unroll
        for (int k = 0; k < 32; k += 2) {
            float4 a  = w4[lane + (k + 0) * 32];
            float4 v  = sx[lane + (k + 0) * 32];
            acc0 += dot4(a, v);
            float4 a2 = w4[lane + (k + 1) * 32];
            float4 v2 = sx[lane + (k + 1) * 32];
            acc1 += dot4(a2, v2);
        }
        float acc = warp_reduce(acc0 + acc1);
        if (lane == 0) g_attn_logits[row] = acc + attn_b[row];
    }
}

// ---------------- launch 2: softmax over 512 logits + reset accumulators ----
__global__ void k_softmax512(float* __restrict__ out_aw) {
    __shared__ float sh[L];
    int t = threadIdx.x;
#pragma unroll
    for (int r = 0; r < H / L; r++) g_att[t + r * L] = 0.f;
    if (t == 0) { g_sumexp = 0.f; g_cnt = 0u; }
    float v = g_attn_logits[t];
    sh[t] = v;
    __syncthreads();
    for (int s = L / 2; s > 0; s >>= 1) {
        if (t < s) sh[t] = fmaxf(sh[t], sh[t + s]);
        __syncthreads();
    }
    float m = sh[0];
    __syncthreads();
    float e = expf(v - m);
    sh[t] = e;
    __syncthreads();
    for (int s = L / 2; s > 0; s >>= 1) {
        if (t < s) sh[t] += sh[t + s];
        __syncthreads();
    }
    float w = e / sh[0];
    g_attn_weights[t] = w;
    out_aw[t] = w;
}

// ---------------- launch 3: attn_applied ----------------
#define AA_ROWS 4
__global__ void k_attn_applied(const float* __restrict__ enc) {
    int j4 = blockIdx.x * blockDim.x + threadIdx.x;   // 0 .. H/4-1
    int i0 = blockIdx.y * AA_ROWS;
    float4 acc = make_float4(0.f, 0.f, 0.f, 0.f);
#pragma unroll
    for (int r = 0; r < AA_ROWS; r++) {
        float w = g_attn_weights[i0 + r];
        float4 e = ((const float4*)enc)[(size_t)(i0 + r) * (H / 4) + j4];
        acc.x += w * e.x; acc.y += w * e.y;
        acc.z += w * e.z; acc.w += w * e.w;
    }
    atomicAdd(&g_att[j4 * 4 + 0], acc.x);
    atomicAdd(&g_att[j4 * 4 + 1], acc.y);
    atomicAdd(&g_att[j4 * 4 + 2], acc.z);
    atomicAdd(&g_att[j4 * 4 + 3], acc.w);
}

// ---------------- launch 4: combined + relu (split-K, 2 warps/row) ---------
// 512 threads = 16 warps; 8 rows/block; warp pair (2r, 2r+1) splits row r.
__global__ void k_comb(const float* __restrict__ W,
                       const float* __restrict__ emb,
                       const int* __restrict__ input,
                       const float* __restrict__ b) {
    __shared__ float4 sx[C2 / 4];    // 16KB: [emb[input] ; g_att]
    __shared__ float sh[16];
    int tid = threadIdx.x;
    const float4* e4 = (const float4*)(emb + (size_t)input[0] * H);
    const float4* a4 = (const float4*)g_att;
    for (int i = tid; i < C2 / 4; i += 512)
        sx[i] = (i < H / 4) ? e4[i] : a4[i - H / 4];
    __syncthreads();
    int wib = tid >> 5, lane = tid & 31;
    int r = wib >> 1, half = wib & 1;
    int row = blockIdx.x * 8 + r;
    const float4* w4 = (const float4*)(W + (size_t)row * C2) + half * 512;
    const float4* xs = sx + half * 512;
    float acc0 = 0.f, acc1 = 0.f;
#pragma unroll
    for (int k = 0; k < 16; k += 2) {
        float4 a  = w4[lane + (k + 0) * 32];
        float4 v  = xs[lane + (k + 0) * 32];
        acc0 += dot4(a, v);
        float4 a2 = w4[lane + (k + 1) * 32];
        float4 v2 = xs[lane + (k + 1) * 32];
        acc1 += dot4(a2, v2);
    }
    float acc = warp_reduce(acc0 + acc1);
    if (lane == 0) sh[wib] = acc;
    __syncthreads();
    if (tid < 8) {
        float y = sh[2 * tid] + sh[2 * tid + 1] + b[blockIdx.x * 8 + tid];
        g_x[blockIdx.x * 8 + tid] = fmaxf(y, 0.f);
    }
}

// ---------------- launch 5: W_ih gates + last-block GRU combine ------------
__global__ void k_gates_ih(const float* __restrict__ W_ih,
                           const float* __restrict__ b_ih,
                           const float* __restrict__ hidden,
                           float* __restrict__ out_h1) {
    __shared__ float4 sx[H / 4];     // 8KB: g_x
    __shared__ bool last;
    int tid = threadIdx.x;
    const float4* x4 = (const float4*)g_x;
    for (int i = tid; i < H / 4; i += 256) sx[i] = x4[i];
    __syncthreads();
    int wib = tid >> 5, lane = tid & 31;
    int row = blockIdx.x * 8 + wib;
    const float4* w4 = (const float4*)(W_ih + (size_t)row * H);
    float acc0 = 0.f, acc1 = 0.f;
#pragma unroll
    for (int k = 0; k < 16; k += 2) {
        float4 a  = w4[lane + (k + 0) * 32];
        float4 v  = sx[lane + (k + 0) * 32];
        acc0 += dot4(a, v);
        float4 a2 = w4[lane + (k + 1) * 32];
        float4 v2 = sx[lane + (k + 1) * 32];
        acc1 += dot4(a2, v2);
    }
    float acc = warp_reduce(acc0 + acc1);
    if (lane == 0) g_gates[row] = acc + b_ih[row];

    // last finishing block performs the GRU combine
    __threadfence();
    if (tid == 0) {
        unsigned c = atomicAdd(&g_cnt, 1u);
        last = (c == gridDim.x - 1);
    }
    __syncthreads();
    if (last) {
        for (int j = tid; j < H; j += 256) {
            float rr = 1.f / (1.f + expf(-(g_gates[j] + g_gates[H3 + j])));
            float z  = 1.f / (1.f + expf(-(g_gates[H + j] + g_gates[H3 + H + j])));
            float n  = tanhf(g_gates[2 * H + j] + rr * g_gates[H3 + 2 * H + j]);
            float hv = (1.f - z) * n + z * hidden[j];
            g_h1[j] = hv;
            out_h1[j] = hv;
        }
    }
}

// ---------------- launch 6: output logits + fused exp-sum ------------------
__global__ void k_out(const float* __restrict__ W,
                      const float* __restrict__ b) {
    __shared__ float4 sx[H / 4];     // 8KB: g_h1
    __shared__ float sh[8];
    int tid = threadIdx.x;
    const float4* x4 = (const float4*)g_h1;
    for (int i = tid; i < H / 4; i += 256) sx[i] = x4[i];
    __syncthreads();
    int wib = tid >> 5, lane = tid & 31;
    int row = blockIdx.x * 8 + wib;
    float e = 0.f;
    if (row < V) {
        const float4* w4 = (const float4*)(W + (size_t)row * H);
        float acc0 = 0.f, acc1 = 0.f;
#pragma unroll
        for (int k = 0; k < 16; k += 2) {
            float4 a  = w4[lane + (k + 0) * 32];
            float4 v  = sx[lane + (k + 0) * 32];
            acc0 += dot4(a, v);
            float4 a2 = w4[lane + (k + 1) * 32];
            float4 v2 = sx[lane + (k + 1) * 32];
            acc1 += dot4(a2, v2);
        }
        float acc = warp_reduce(acc0 + acc1);
        if (lane == 0) {
            acc += b[row];
            g_logits[row] = acc;
            e = expf(acc);   // no max shift: |logit| is small (s=0.02, bounded h1)
        }
    }
    if (lane == 0) sh[wib] = e;
    __syncthreads();
    if (tid == 0)
        atomicAdd(&g_sumexp,
                  sh[0] + sh[1] + sh[2] + sh[3] + sh[4] + sh[5] + sh[6] + sh[7]);
}

// ---------------- launch 7: write log-probs ----------------
__global__ void k_write_logprobs(float* __restrict__ out) {
    int i = blockIdx.x * blockDim.x + threadIdx.x;
    if (i < V) out[i] = g_logits[i] - logf(g_sumexp);
}

// ---------------- launch ----------------
extern "C" void kernel_launch(void* const* d_in, const int* in_sizes, int n_in,
                              void* d_out, int out_size) {
    const int*   input   = (const int*)  d_in[0];
    const float* hidden  = (const float*)d_in[1];
    const float* enc     = (const float*)d_in[2];
    const float* emb     = (const float*)d_in[3];
    const float* attn_W  = (const float*)d_in[4];
    const float* attn_b  = (const float*)d_in[5];
    const float* comb_W  = (const float*)d_in[6];
    const float* comb_b  = (const float*)d_in[7];
    const float* W_ih    = (const float*)d_in[8];
    const float* W_hh    = (const float*)d_in[9];
    const float* b_ih    = (const float*)d_in[10];
    const float* b_hh    = (const float*)d_in[11];
    const float* out_W   = (const float*)d_in[12];
    const float* out_b   = (const float*)d_in[13];

    float* out = (float*)d_out;
    float* out_logp = out;           // [V]
    float* out_h1   = out + V;       // [H]
    float* out_aw   = out + V + H;   // [L]

    // 1. fused: W_hh gate matvec (6144x2048) + attention logits (512x4096)
    k_fused1<<<HH_BLOCKS + ATT_BLOCKS, 256>>>(W_hh, b_hh, hidden,
                                              attn_W, attn_b, emb, input);
    // 2. softmax over L (+ reset g_att / g_sumexp / g_cnt)
    k_softmax512<<<1, L>>>(out_aw);
    // 3. attn_applied -> g_att
    {
        dim3 grid((H / 4) / 128, L / AA_ROWS);
        k_attn_applied<<<grid, 128>>>(enc);
    }
    // 4. combined + relu (split-K)
    k_comb<<<H / 8, 512>>>(comb_W, emb, input, comb_b);
    // 5. W_ih gates + last-block GRU
    k_gates_ih<<<H3 / 8, 256>>>(W_ih, b_ih, hidden, out_h1);
    // 6. output logits + exp-sum
    k_out<<<(V + 7) / 8, 256>>>(out_W, out_b);
    // 7. write log-probs
    k_write_logprobs<<<(V + 255) / 256, 256>>>(out_logp);
}

// round 5
// speedup vs baseline: 1.0963x; 1.0963x over previous
#include <cuda_runtime.h>
#include <math.h>

// Problem dims
#define H   2048
#define V   50257
#define L   512
#define H3  6144
#define C2  4096   // 2*H

// ---------------- device scratch ----------------
__device__ float g_att[H];
__device__ float g_attn_logits[L];
__device__ float g_attn_weights[L];
__device__ float g_x[H];
__device__ float g_gates[2 * H3];    // ih gates [0,6144), hh gates [6144,12288)
__device__ float g_h1[H];
__device__ float g_logits[V];
__device__ float g_sumexp;

__device__ __forceinline__ float warp_reduce(float v) {
#pragma unroll
    for (int o = 16; o > 0; o >>= 1)
        v += __shfl_xor_sync(0xFFFFFFFFu, v, o);
    return v;
}

__device__ __forceinline__ float dot4(float4 a, float4 v) {
    return a.x * v.x + a.y * v.y + a.z * v.z + a.w * v.w;
}

// Batched matvec core: NB batches; each batch stages 8 float4 W-loads into
// registers (MLP=8) before FMAs against smem-resident x. Covers NB*1024 floats.
template <int NB>
__device__ __forceinline__ float mv_row(const float4* __restrict__ w4,
                                        const float4* __restrict__ sx,
                                        int lane) {
    float acc0 = 0.f, acc1 = 0.f, acc2 = 0.f, acc3 = 0.f;
#pragma unroll
    for (int bb = 0; bb < NB; bb++) {
        const float4* wb = w4 + bb * 256;
        const float4* xb = sx + bb * 256;
        float4 a0 = wb[lane + 0 * 32];
        float4 a1 = wb[lane + 1 * 32];
        float4 a2 = wb[lane + 2 * 32];
        float4 a3 = wb[lane + 3 * 32];
        float4 a4 = wb[lane + 4 * 32];
        float4 a5 = wb[lane + 5 * 32];
        float4 a6 = wb[lane + 6 * 32];
        float4 a7 = wb[lane + 7 * 32];
        acc0 += dot4(a0, xb[lane + 0 * 32]);
        acc1 += dot4(a1, xb[lane + 1 * 32]);
        acc2 += dot4(a2, xb[lane + 2 * 32]);
        acc3 += dot4(a3, xb[lane + 3 * 32]);
        acc0 += dot4(a4, xb[lane + 4 * 32]);
        acc1 += dot4(a5, xb[lane + 5 * 32]);
        acc2 += dot4(a6, xb[lane + 6 * 32]);
        acc3 += dot4(a7, xb[lane + 7 * 32]);
    }
    return (acc0 + acc1) + (acc2 + acc3);
}

// ---------------- launch 1: attention logits (512 rows x 4096) -------------
__global__ void k_attn(const float* __restrict__ attn_W,
                       const float* __restrict__ attn_b,
                       const float* __restrict__ emb,
                       const int* __restrict__ input,
                       const float* __restrict__ hidden) {
    __shared__ float4 sx[C2 / 4];    // 16KB: [emb[input] ; hidden]
    int tid = threadIdx.x;
    const float4* e4 = (const float4*)(emb + (size_t)input[0] * H);
    const float4* h4 = (const float4*)hidden;
    for (int i = tid; i < C2 / 4; i += 256)
        sx[i] = (i < H / 4) ? e4[i] : h4[i - H / 4];
    __syncthreads();
    int wib = tid >> 5, lane = tid & 31;
    int row = blockIdx.x * 8 + wib;
    const float4* w4 = (const float4*)(attn_W + (size_t)row * C2);
    float acc = warp_reduce(mv_row<4>(w4, sx, lane));
    if (lane == 0) g_attn_logits[row] = acc + attn_b[row];
}

// ---------------- launch 2: softmax over 512 + reset accumulators ----------
__global__ void k_softmax512(float* __restrict__ out_aw) {
    __shared__ float sh[L];
    int t = threadIdx.x;
#pragma unroll
    for (int r = 0; r < H / L; r++) g_att[t + r * L] = 0.f;
    if (t == 0) g_sumexp = 0.f;
    float v = g_attn_logits[t];
    sh[t] = v;
    __syncthreads();
    for (int s = L / 2; s > 0; s >>= 1) {
        if (t < s) sh[t] = fmaxf(sh[t], sh[t + s]);
        __syncthreads();
    }
    float m = sh[0];
    __syncthreads();
    float e = expf(v - m);
    sh[t] = e;
    __syncthreads();
    for (int s = L / 2; s > 0; s >>= 1) {
        if (t < s) sh[t] += sh[t + s];
        __syncthreads();
    }
    float w = e / sh[0];
    g_attn_weights[t] = w;
    out_aw[t] = w;
}

// ---------------- launch 3: attn_applied -----------------------------------
#define AA_ROWS 4
__global__ void k_attn_applied(const float* __restrict__ enc) {
    int j4 = blockIdx.x * blockDim.x + threadIdx.x;   // 0 .. H/4-1
    int i0 = blockIdx.y * AA_ROWS;
    float4 acc = make_float4(0.f, 0.f, 0.f, 0.f);
#pragma unroll
    for (int r = 0; r < AA_ROWS; r++) {
        float w = g_attn_weights[i0 + r];
        float4 e = ((const float4*)enc)[(size_t)(i0 + r) * (H / 4) + j4];
        acc.x += w * e.x; acc.y += w * e.y;
        acc.z += w * e.z; acc.w += w * e.w;
    }
    atomicAdd(&g_att[j4 * 4 + 0], acc.x);
    atomicAdd(&g_att[j4 * 4 + 1], acc.y);
    atomicAdd(&g_att[j4 * 4 + 2], acc.z);
    atomicAdd(&g_att[j4 * 4 + 3], acc.w);
}

// ---------------- launch 4: combined + relu (split-K, 2 warps/row) ---------
__global__ void k_comb(const float* __restrict__ W,
                       const float* __restrict__ emb,
                       const int* __restrict__ input,
                       const float* __restrict__ b) {
    __shared__ float4 sx[C2 / 4];    // 16KB: [emb[input] ; g_att]
    __shared__ float sh[16];
    int tid = threadIdx.x;
    const float4* e4 = (const float4*)(emb + (size_t)input[0] * H);
    const float4* a4 = (const float4*)g_att;
    for (int i = tid; i < C2 / 4; i += 512)
        sx[i] = (i < H / 4) ? e4[i] : a4[i - H / 4];
    __syncthreads();
    int wib = tid >> 5, lane = tid & 31;
    int r = wib >> 1, half = wib & 1;
    int row = blockIdx.x * 8 + r;
    const float4* w4 = (const float4*)(W + (size_t)row * C2) + half * 512;
    float acc = warp_reduce(mv_row<2>(w4, sx + half * 512, lane));
    if (lane == 0) sh[wib] = acc;
    __syncthreads();
    if (tid < 8) {
        float y = sh[2 * tid] + sh[2 * tid + 1] + b[blockIdx.x * 8 + tid];
        g_x[blockIdx.x * 8 + tid] = fmaxf(y, 0.f);
    }
}

// ---------------- launch 5: all GRU gate matvecs (12288 rows x 2048) -------
// blocks [0,768): ih gates on g_x; blocks [768,1536): hh gates on hidden.
__global__ void k_gates(const float* __restrict__ W_ih,
                        const float* __restrict__ W_hh,
                        const float* __restrict__ b_ih,
                        const float* __restrict__ b_hh,
                        const float* __restrict__ hidden) {
    __shared__ float4 sx[H / 4];     // 8KB
    int tid = threadIdx.x;
    int blk = blockIdx.x;
    bool ih = blk < (H3 / 8);
    const float4* x4 = ih ? (const float4*)g_x : (const float4*)hidden;
    for (int i = tid; i < H / 4; i += 256) sx[i] = x4[i];
    __syncthreads();
    int wib = tid >> 5, lane = tid & 31;
    int r = (ih ? blk : blk - H3 / 8) * 8 + wib;
    const float* W = ih ? W_ih : W_hh;
    const float* b = ih ? b_ih : b_hh;
    const float4* w4 = (const float4*)(W + (size_t)r * H);
    float acc = warp_reduce(mv_row<2>(w4, sx, lane));
    if (lane == 0) g_gates[(ih ? 0 : H3) + r] = acc + b[r];
}

// ---------------- launch 6: GRU combine ----------------
__global__ void k_gru(const float* __restrict__ hidden, float* __restrict__ out_h1) {
    int j = blockIdx.x * blockDim.x + threadIdx.x;
    if (j >= H) return;
    float rr = 1.f / (1.f + expf(-(g_gates[j] + g_gates[H3 + j])));
    float z  = 1.f / (1.f + expf(-(g_gates[H + j] + g_gates[H3 + H + j])));
    float n  = tanhf(g_gates[2 * H + j] + rr * g_gates[H3 + 2 * H + j]);
    float hv = (1.f - z) * n + z * hidden[j];
    g_h1[j] = hv;
    out_h1[j] = hv;
}

// ---------------- launch 7: output logits + fused exp-sum ------------------
__global__ void __launch_bounds__(256) k_out(const float* __restrict__ W,
                                             const float* __restrict__ b) {
    __shared__ float4 sx[H / 4];     // 8KB: g_h1
    __shared__ float sh[8];
    int tid = threadIdx.x;
    const float4* x4 = (const float4*)g_h1;
    for (int i = tid; i < H / 4; i += 256) sx[i] = x4[i];
    __syncthreads();
    int wib = tid >> 5, lane = tid & 31;
    int row = blockIdx.x * 8 + wib;
    float e = 0.f;
    if (row < V) {
        const float4* w4 = (const float4*)(W + (size_t)row * H);
        float acc = warp_reduce(mv_row<2>(w4, sx, lane));
        if (lane == 0) {
            acc += b[row];
            g_logits[row] = acc;
            e = expf(acc);   // no max shift: |logit| is small (s=0.02, bounded h1)
        }
    }
    if (lane == 0) sh[wib] = e;
    __syncthreads();
    if (tid == 0)
        atomicAdd(&g_sumexp,
                  sh[0] + sh[1] + sh[2] + sh[3] + sh[4] + sh[5] + sh[6] + sh[7]);
}

// ---------------- launch 8: write log-probs ----------------
__global__ void k_write_logprobs(float* __restrict__ out) {
    int i = blockIdx.x * blockDim.x + threadIdx.x;
    if (i < V) out[i] = g_logits[i] - logf(g_sumexp);
}

// ---------------- launch ----------------
extern "C" void kernel_launch(void* const* d_in, const int* in_sizes, int n_in,
                              void* d_out, int out_size) {
    const int*   input   = (const int*)  d_in[0];
    const float* hidden  = (const float*)d_in[1];
    const float* enc     = (const float*)d_in[2];
    const float* emb     = (const float*)d_in[3];
    const float* attn_W  = (const float*)d_in[4];
    const float* attn_b  = (const float*)d_in[5];
    const float* comb_W  = (const float*)d_in[6];
    const float* comb_b  = (const float*)d_in[7];
    const float* W_ih    = (const float*)d_in[8];
    const float* W_hh    = (const float*)d_in[9];
    const float* b_ih    = (const float*)d_in[10];
    const float* b_hh    = (const float*)d_in[11];
    const float* out_W   = (const float*)d_in[12];
    const float* out_b   = (const float*)d_in[13];

    float* out = (float*)d_out;
    float* out_logp = out;           // [V]
    float* out_h1   = out + V;       // [H]
    float* out_aw   = out + V + H;   // [L]

    // 1. attention logits
    k_attn<<<L / 8, 256>>>(attn_W, attn_b, emb, input, hidden);
    // 2. softmax over L (+ reset g_att / g_sumexp)
    k_softmax512<<<1, L>>>(out_aw);
    // 3. attn_applied
    {
        dim3 grid((H / 4) / 128, L / AA_ROWS);
        k_attn_applied<<<grid, 128>>>(enc);
    }
    // 4. combined + relu (split-K)
    k_comb<<<H / 8, 512>>>(comb_W, emb, input, comb_b);
    // 5. GRU gates (ih + hh in one grid)
    k_gates<<<2 * (H3 / 8), 256>>>(W_ih, W_hh, b_ih, b_hh, hidden);
    // 6. GRU combine
    k_gru<<<(H + 255) / 256, 256>>>(hidden, out_h1);
    // 7. output logits + exp-sum
    k_out<<<(V + 7) / 8, 256>>>(out_W, out_b);
    // 8. write log-probs
    k_write_logprobs<<<(V + 255) / 256, 256>>>(out_logp);
}